// round 2
// baseline (speedup 1.0000x reference)
#include <cuda_runtime.h>
#include <cstdint>

#define D_DIM 128

// ---------------- device scratch (no allocations allowed) ----------------
__device__ double g_dots_acc;
__device__ float  g_M[D_DIM * D_DIM];   // M = U U^T
__device__ float  g_W[D_DIM * D_DIM];   // W = U diag(cnt) U^T
__device__ float  g_cnt[4096];          // histogram of G (P <= 4096)
__device__ int    g_idx64;              // 1 if index arrays are int64, 0 if int32

__device__ __forceinline__ long long ld_idx(const void* p, long long i, int is64) {
    if (is64) return ((const long long*)p)[i];
    return (long long)((const int*)p)[i];
}

// ---------------- kernel Z: zero scratch + detect index dtype (parallel) ----
__global__ void k_init(const void* merge_idx, long long N, int P) {
    long long tid = (long long)blockIdx.x * blockDim.x + threadIdx.x;
    long long stride = (long long)gridDim.x * blockDim.x;
    for (long long i = tid; i < (long long)D_DIM * D_DIM; i += stride) {
        g_M[i] = 0.f;
        g_W[i] = 0.f;
    }
    for (long long i = tid; i < P; i += stride) g_cnt[i] = 0.f;
    if (blockIdx.x == 0 && threadIdx.x < 32) {
        // Parallel dtype probe: read first up-to-64 entries as int64.
        // int32 data reinterpreted as int64 has a nonzero high word -> out of range.
        const long long* p64 = (const long long*)merge_idx;
        int m = (int)(N < 64 ? N : 64);
        int bad = 0;
        for (int i = threadIdx.x; i < m; i += 32) {
            long long v = p64[i];
            bad |= (v < 0 || v >= N) ? 1 : 0;
        }
        unsigned b = __ballot_sync(0xFFFFFFFFu, bad);
        if (threadIdx.x == 0) {
            g_idx64 = (b == 0) ? 1 : 0;
            g_dots_acc = 0.0;
        }
    }
}

// ---------------- kernel C: histogram of G ----------------
__global__ void k_count(const void* Gp, int total) {
    int is64 = g_idx64;
    int i = blockIdx.x * blockDim.x + threadIdx.x;
    if (i < total) {
        int g = (int)ld_idx(Gp, i, is64);
        atomicAdd(&g_cnt[g], 1.0f);
    }
}

// ---------------- kernel MW: M = U U^T,  W = U diag(cnt) U^T ----------------
__global__ void k_mw(const float* __restrict__ U, int P) {
    __shared__ float sh[16][D_DIM];   // 16 columns of U
    __shared__ float shc[16];

    int chunk = blockIdx.x >> 2;
    int quad  = blockIdx.x & 3;
    int p0 = chunk * 16;
    int tid = threadIdx.x;

    for (int e = tid; e < 16 * D_DIM; e += blockDim.x) {
        int d = e >> 4, pc = e & 15;
        int p = p0 + pc;
        sh[pc][d] = (p < P) ? U[(size_t)d * P + p] : 0.f;
    }
    if (tid < 16) {
        int p = p0 + tid;
        shc[tid] = (p < P) ? g_cnt[p] : 0.f;
    }
    __syncthreads();

    int ti = tid & 15, tj = tid >> 4;
    int i0 = (quad & 1) * 64 + ti * 4;
    int j0 = (quad >> 1) * 64 + tj * 4;

    float m[4][4] = {{0}}, w[4][4] = {{0}};
#pragma unroll
    for (int pc = 0; pc < 16; pc++) {
        float c = shc[pc];
        float a[4], ca[4], b[4];
#pragma unroll
        for (int x = 0; x < 4; x++) { a[x] = sh[pc][i0 + x]; ca[x] = c * a[x]; }
#pragma unroll
        for (int y = 0; y < 4; y++) b[y] = sh[pc][j0 + y];
#pragma unroll
        for (int x = 0; x < 4; x++)
#pragma unroll
            for (int y = 0; y < 4; y++) {
                m[x][y] += a[x] * b[y];
                w[x][y] += ca[x] * b[y];
            }
    }

#pragma unroll
    for (int x = 0; x < 4; x++)
#pragma unroll
        for (int y = 0; y < 4; y++) {
            int idx = (i0 + x) * D_DIM + (j0 + y);
            atomicAdd(&g_M[idx], m[x][y]);
            atomicAdd(&g_W[idx], w[x][y]);
        }
}

// ---------------- kernel D: the big HBM-bound dots pass ----------------
// 4 columns j per thread; float4 ub loads + single broadcast uu load on the
// fast path (contiguous merge_idx, uniform seg within the 4-pack).
__global__ void __launch_bounds__(256)
k_dots(const float* __restrict__ Ub, const float* __restrict__ U,
       const void* midx, const void* segs,
       long long N, int P) {
    int is64 = g_idx64;
    long long j0 = ((long long)blockIdx.x * blockDim.x + threadIdx.x) * 4;

    double val = 0.0;
    if (j0 < N) {
        int npack = (int)((N - j0) < 4 ? (N - j0) : 4);
        long long mi[4]; int gg[4];
#pragma unroll
        for (int x = 0; x < 4; x++) {
            long long jj = (x < npack) ? (j0 + x) : j0;
            mi[x] = ld_idx(midx, jj, is64);
            gg[x] = (int)ld_idx(segs, jj, is64);
        }
        float a0 = 0.f, a1 = 0.f, a2 = 0.f, a3 = 0.f;

        bool fast = (npack == 4) &&
                    (mi[1] == mi[0] + 1) && (mi[2] == mi[0] + 2) && (mi[3] == mi[0] + 3) &&
                    ((N & 3) == 0) && ((mi[0] & 3) == 0);

        if (fast) {
            const float* uu0 = U + gg[0];
            if (gg[0] == gg[1] && gg[1] == gg[2] && gg[2] == gg[3]) {
                // fully uniform pack: 1 float4 + 1 scalar load per d
#pragma unroll 8
                for (int d = 0; d < D_DIM; d++) {
                    float4 v = __ldg((const float4*)(Ub + (size_t)d * N + mi[0]));
                    float u = __ldg(uu0 + (size_t)d * P);
                    a0 += v.x * u; a1 += v.y * u; a2 += v.z * u; a3 += v.w * u;
                }
            } else {
                const float* uu1 = U + gg[1];
                const float* uu2 = U + gg[2];
                const float* uu3 = U + gg[3];
#pragma unroll 8
                for (int d = 0; d < D_DIM; d++) {
                    float4 v = __ldg((const float4*)(Ub + (size_t)d * N + mi[0]));
                    size_t o = (size_t)d * P;
                    a0 += v.x * __ldg(uu0 + o);
                    a1 += v.y * __ldg(uu1 + o);
                    a2 += v.z * __ldg(uu2 + o);
                    a3 += v.w * __ldg(uu3 + o);
                }
            }
        } else {
            // generic scalar path (tails / non-contiguous merge_idx)
            float acc[4] = {0.f, 0.f, 0.f, 0.f};
#pragma unroll 4
            for (int d = 0; d < D_DIM; d++) {
                size_t oP = (size_t)d * P;
                size_t oN = (size_t)d * N;
#pragma unroll
                for (int x = 0; x < 4; x++) {
                    if (x < npack)
                        acc[x] += __ldg(Ub + oN + mi[x]) * __ldg(U + oP + gg[x]);
                }
            }
            a0 = acc[0]; a1 = (npack > 1) ? acc[1] : 0.f;
            a2 = (npack > 2) ? acc[2] : 0.f;
            a3 = (npack > 3) ? acc[3] : 0.f;
            if (npack < 2) a1 = 0.f;
            if (npack < 3) a2 = 0.f;
            if (npack < 4) a3 = 0.f;
        }
        val = (double)a0 * a0 + (double)a1 * a1 + (double)a2 * a2 + (double)a3 * a3;
    }

    // block reduce in double
    __shared__ double red[8];
    unsigned mask = 0xFFFFFFFFu;
#pragma unroll
    for (int off = 16; off > 0; off >>= 1)
        val += __shfl_down_sync(mask, val, off);
    int lane = threadIdx.x & 31, warp = threadIdx.x >> 5;
    if (lane == 0) red[warp] = val;
    __syncthreads();
    if (warp == 0) {
        double s = (lane < 8) ? red[lane] : 0.0;
#pragma unroll
        for (int off = 4; off > 0; off >>= 1)
            s += __shfl_down_sync(mask, s, off);
        if (lane == 0) atomicAdd(&g_dots_acc, s);
    }
}

// ---------------- kernel F: trace(M .* W) + finalize ----------------
__global__ void k_final(float* out, double inv_den) {
    __shared__ double red[8];
    int tid = threadIdx.x;
    double s = 0.0;
    for (int i = tid; i < D_DIM * D_DIM; i += blockDim.x)
        s += (double)g_M[i] * (double)g_W[i];
    unsigned mask = 0xFFFFFFFFu;
#pragma unroll
    for (int off = 16; off > 0; off >>= 1)
        s += __shfl_down_sync(mask, s, off);
    int lane = tid & 31, warp = tid >> 5;
    if (lane == 0) red[warp] = s;
    __syncthreads();
    if (warp == 0) {
        double t = (lane < 8) ? red[lane] : 0.0;
#pragma unroll
        for (int off = 4; off > 0; off >>= 1)
            t += __shfl_down_sync(mask, t, off);
        if (lane == 0)
            out[0] = (float)(-0.5 * g_dots_acc - 0.5 * t * inv_den);
    }
}

// ---------------- launch ----------------
extern "C" void kernel_launch(void* const* d_in, const int* in_sizes, int n_in,
                              void* d_out, int out_size) {
    const float* U_base = (const float*)d_in[0];
    const float* U      = (const float*)d_in[1];
    const void*  midx   = d_in[2];
    const void*  segs   = d_in[3];
    const void*  Gp     = d_in[4];

    long long N = in_sizes[2];
    int D = (int)((long long)in_sizes[0] / N); // = 128
    int P = in_sizes[1] / D;                   // = 1024
    int PK = in_sizes[4];                      // P*K
    int K = PK / P;
    (void)D; (void)n_in;

    float* out = (float*)d_out;
    (void)out_size;

    k_init<<<132, 256>>>(midx, N, P);
    k_count<<<(PK + 255) / 256, 256>>>(Gp, PK);
    int nchunk = (P + 15) / 16;
    k_mw<<<nchunk * 4, 256>>>(U, P);

    long long nblk = (N + 1023) / 1024;   // 4 j per thread, 256 threads
    k_dots<<<(unsigned)nblk, 256>>>(U_base, U, midx, segs, N, P);

    double inv_den = 1.0 / ((double)P * (double)K * (double)P);
    k_final<<<1, 256>>>(out, inv_den);
}

// round 3
// speedup vs baseline: 1.2184x; 1.2184x over previous
#include <cuda_runtime.h>
#include <cstdint>

#define D_DIM 128

// ---------------- device scratch (no allocations allowed) ----------------
__device__ double g_dots_acc;
__device__ float  g_M[D_DIM * D_DIM];   // M = U U^T
__device__ float  g_W[D_DIM * D_DIM];   // W = U diag(cnt) U^T
__device__ float  g_cnt[4096];          // histogram of G (P <= 4096)

__device__ __forceinline__ long long ld_idx(const void* p, long long i, int is64) {
    if (is64) return ((const long long*)p)[i];
    return (long long)((const int*)p)[i];
}

// Block-level dtype probe: warp 0 reads first <=32 int64 entries of merge_idx.
// int32 data reinterpreted as int64 has nonzero high words -> out of [0,N).
__device__ __forceinline__ int probe_is64(const void* merge_idx, long long N) {
    __shared__ int s_is64;
    if (threadIdx.x < 32) {
        const long long* p64 = (const long long*)merge_idx;
        int m = (int)(N < 32 ? N : 32);
        int bad = 0;
        if ((int)threadIdx.x < m) {
            long long v = p64[threadIdx.x];
            bad = (v < 0 || v >= N) ? 1 : 0;
        }
        unsigned b = __ballot_sync(0xFFFFFFFFu, bad);
        if (threadIdx.x == 0) s_is64 = (b == 0) ? 1 : 0;
    }
    __syncthreads();
    return s_is64;
}

// ---------------- kernel H: histogram of G ----------------
__global__ void k_hist(const void* Gp, int total, const void* midx, long long N) {
    int is64 = probe_is64(midx, N);
    int i = blockIdx.x * blockDim.x + threadIdx.x;
    if (i < total) {
        int g = (int)ld_idx(Gp, i, is64);
        atomicAdd(&g_cnt[g], 1.0f);
    }
}

// ---------------- kernel MW: M = U U^T,  W = U diag(cnt) U^T ----------------
// grid = ngrp*4 blocks. Each block: 8 consecutive 16-column chunks (register
// accumulated), one 64x64 quadrant, then ONE atomic store set (32/thread).
__global__ void k_mw(const float* __restrict__ U, int P, int ngrp) {
    __shared__ float sh[16][D_DIM];
    __shared__ float shc[16];

    int grp  = blockIdx.x >> 2;
    int quad = blockIdx.x & 3;
    int tid = threadIdx.x;

    int ti = tid & 15, tj = tid >> 4;
    int i0 = (quad & 1) * 64 + ti * 4;
    int j0 = (quad >> 1) * 64 + tj * 4;

    float m[4][4] = {{0}}, w[4][4] = {{0}};

    for (int c = 0; c < 8; c++) {
        int p0 = (grp * 8 + c) * 16;
        __syncthreads();
        for (int e = tid; e < 16 * D_DIM; e += blockDim.x) {
            int d = e >> 4, pc = e & 15;
            int p = p0 + pc;
            sh[pc][d] = (p < P) ? U[(size_t)d * P + p] : 0.f;
        }
        if (tid < 16) {
            int p = p0 + tid;
            shc[tid] = (p < P) ? g_cnt[p] : 0.f;
        }
        __syncthreads();

#pragma unroll
        for (int pc = 0; pc < 16; pc++) {
            float cw = shc[pc];
            float a[4], ca[4], b[4];
#pragma unroll
            for (int x = 0; x < 4; x++) { a[x] = sh[pc][i0 + x]; ca[x] = cw * a[x]; }
#pragma unroll
            for (int y = 0; y < 4; y++) b[y] = sh[pc][j0 + y];
#pragma unroll
            for (int x = 0; x < 4; x++)
#pragma unroll
                for (int y = 0; y < 4; y++) {
                    m[x][y] += a[x] * b[y];
                    w[x][y] += ca[x] * b[y];
                }
        }
    }

#pragma unroll
    for (int x = 0; x < 4; x++)
#pragma unroll
        for (int y = 0; y < 4; y++) {
            int idx = (i0 + x) * D_DIM + (j0 + y);
            atomicAdd(&g_M[idx], m[x][y]);
            atomicAdd(&g_W[idx], w[x][y]);
        }
}

// ---------------- kernel D: the big HBM-bound dots pass ----------------
// 4 columns j per thread; float4 ub load + 4 cached uu loads per d on the
// fast path (contiguous merge_idx). Per-thread fallback for tails/general.
__global__ void __launch_bounds__(128, 8)
k_dots(const float* __restrict__ Ub, const float* __restrict__ U,
       const void* midx, const void* segs,
       long long N, int P) {
    int is64 = probe_is64(midx, N);
    long long j0 = ((long long)blockIdx.x * blockDim.x + threadIdx.x) * 4;

    double val = 0.0;
    if (j0 < N) {
        int npack = (int)((N - j0) < 4 ? (N - j0) : 4);
        long long mi0 = ld_idx(midx, j0, is64);
        long long mi1, mi2, mi3;
        int g0, g1, g2, g3;
        g0 = (int)ld_idx(segs, j0, is64);
        if (npack == 4) {
            mi1 = ld_idx(midx, j0 + 1, is64);
            mi2 = ld_idx(midx, j0 + 2, is64);
            mi3 = ld_idx(midx, j0 + 3, is64);
            g1 = (int)ld_idx(segs, j0 + 1, is64);
            g2 = (int)ld_idx(segs, j0 + 2, is64);
            g3 = (int)ld_idx(segs, j0 + 3, is64);
        } else {
            mi1 = mi2 = mi3 = mi0; g1 = g2 = g3 = g0;
        }

        float a0 = 0.f, a1 = 0.f, a2 = 0.f, a3 = 0.f;

        bool fast = (npack == 4) && ((N & 3) == 0) &&
                    (mi0 == j0) && (mi1 == j0 + 1) && (mi2 == j0 + 2) && (mi3 == j0 + 3);

        if (fast) {
            const float* pb = Ub + j0;
            size_t oN = 0, oP = 0;
#pragma unroll 8
            for (int d = 0; d < D_DIM; d++) {
                float4 v = __ldg((const float4*)(pb + oN));
                a0 += v.x * __ldg(U + oP + g0);
                a1 += v.y * __ldg(U + oP + g1);
                a2 += v.z * __ldg(U + oP + g2);
                a3 += v.w * __ldg(U + oP + g3);
                oN += (size_t)N; oP += (size_t)P;
            }
        } else {
            size_t oN = 0, oP = 0;
#pragma unroll 1
            for (int d = 0; d < D_DIM; d++) {
                a0 += __ldg(Ub + oN + mi0) * __ldg(U + oP + g0);
                if (npack > 1) a1 += __ldg(Ub + oN + mi1) * __ldg(U + oP + g1);
                if (npack > 2) a2 += __ldg(Ub + oN + mi2) * __ldg(U + oP + g2);
                if (npack > 3) a3 += __ldg(Ub + oN + mi3) * __ldg(U + oP + g3);
                oN += (size_t)N; oP += (size_t)P;
            }
        }
        val = (double)a0 * a0 + (double)a1 * a1 + (double)a2 * a2 + (double)a3 * a3;
    }

    // block reduce (128 threads) in double
    __shared__ double red[4];
    unsigned mask = 0xFFFFFFFFu;
#pragma unroll
    for (int off = 16; off > 0; off >>= 1)
        val += __shfl_down_sync(mask, val, off);
    int lane = threadIdx.x & 31, warp = threadIdx.x >> 5;
    if (lane == 0) red[warp] = val;
    __syncthreads();
    if (warp == 0) {
        double s = (lane < 4) ? red[lane] : 0.0;
        s += __shfl_down_sync(mask, s, 2);
        s += __shfl_down_sync(mask, s, 1);
        if (lane == 0) atomicAdd(&g_dots_acc, s);
    }
}

// ---------------- kernel F: trace(M .* W) + finalize ----------------
__global__ void k_final(float* out, double inv_den) {
    __shared__ double red[8];
    int tid = threadIdx.x;
    double s = 0.0;
    for (int i = tid; i < D_DIM * D_DIM; i += blockDim.x)
        s += (double)g_M[i] * (double)g_W[i];
    unsigned mask = 0xFFFFFFFFu;
#pragma unroll
    for (int off = 16; off > 0; off >>= 1)
        s += __shfl_down_sync(mask, s, off);
    int lane = tid & 31, warp = tid >> 5;
    if (lane == 0) red[warp] = s;
    __syncthreads();
    if (warp == 0) {
        double t = (lane < 8) ? red[lane] : 0.0;
#pragma unroll
        for (int off = 4; off > 0; off >>= 1)
            t += __shfl_down_sync(mask, t, off);
        if (lane == 0)
            out[0] = (float)(-0.5 * g_dots_acc - 0.5 * t * inv_den);
    }
}

// ---------------- launch ----------------
extern "C" void kernel_launch(void* const* d_in, const int* in_sizes, int n_in,
                              void* d_out, int out_size) {
    const float* U_base = (const float*)d_in[0];
    const float* U      = (const float*)d_in[1];
    const void*  midx   = d_in[2];
    const void*  segs   = d_in[3];
    const void*  Gp     = d_in[4];

    long long N = in_sizes[2];
    int D = (int)((long long)in_sizes[0] / N); // = 128
    int P = in_sizes[1] / D;                   // = 1024
    int PK = in_sizes[4];                      // P*K
    int K = PK / P;
    (void)D; (void)n_in;

    float* out = (float*)d_out;
    (void)out_size;

    // Zero scratch via memset nodes (graph-capturable, no allocation).
    void *pM, *pW, *pC, *pA;
    cudaGetSymbolAddress(&pM, g_M);
    cudaGetSymbolAddress(&pW, g_W);
    cudaGetSymbolAddress(&pC, g_cnt);
    cudaGetSymbolAddress(&pA, g_dots_acc);
    cudaMemsetAsync(pM, 0, D_DIM * D_DIM * sizeof(float));
    cudaMemsetAsync(pW, 0, D_DIM * D_DIM * sizeof(float));
    cudaMemsetAsync(pC, 0, 4096 * sizeof(float));
    cudaMemsetAsync(pA, 0, sizeof(double));

    // H: histogram of G (self-probes index dtype)
    k_hist<<<(PK + 255) / 256, 256>>>(Gp, PK, midx, N);

    // MW: dual weighted outer-product, 8 chunks per block
    int nchunk = (P + 15) / 16;
    int ngrp = (nchunk + 7) / 8;
    k_mw<<<ngrp * 4, 256>>>(U, P, ngrp);

    // D: main HBM-bound pass (4 j per thread, 128 threads/block)
    long long nblk = (N + 511) / 512;
    k_dots<<<(unsigned)nblk, 128>>>(U_base, U, midx, segs, N, P);

    // F: finalize
    double inv_den = 1.0 / ((double)P * (double)K * (double)P);
    k_final<<<1, 256>>>(out, inv_den);
}

// round 6
// speedup vs baseline: 1.4009x; 1.1498x over previous
#include <cuda_runtime.h>
#include <cstdint>

#define D_DIM 128

// ---------------- device scratch: single struct -> one memset ----------------
// Layout: 16B-aligned arrays FIRST (k_final does float4 loads on M/W),
// scalar accumulator last.
struct alignas(16) Scratch {
    float  M[D_DIM * D_DIM];    // M = U U^T           (offset 0)
    float  W[D_DIM * D_DIM];    // W = U diag(cnt) U^T (offset 64KB, 16B-aligned)
    float  cnt[4096];           // histogram of G
    double acc;                 // dots accumulator
};
__device__ Scratch g_s;

__device__ __forceinline__ long long ld_idx(const void* p, long long i, int is64) {
    if (is64) return ((const long long*)p)[i];
    return (long long)((const int*)p)[i];
}

// Block-level dtype probe: warp 0 reads first <=32 int64 entries of merge_idx.
// int32 data reinterpreted as int64 has nonzero high words -> out of [0,N).
__device__ __forceinline__ int probe_is64(const void* merge_idx, long long N) {
    __shared__ int s_is64;
    if (threadIdx.x < 32) {
        const long long* p64 = (const long long*)merge_idx;
        int m = (int)(N < 32 ? N : 32);
        int bad = 0;
        if ((int)threadIdx.x < m) {
            long long v = p64[threadIdx.x];
            bad = (v < 0 || v >= N) ? 1 : 0;
        }
        unsigned b = __ballot_sync(0xFFFFFFFFu, bad);
        if (threadIdx.x == 0) s_is64 = (b == 0) ? 1 : 0;
    }
    __syncthreads();
    return s_is64;
}

// ---------------- kernel H: histogram of G ----------------
__global__ void k_hist(const void* Gp, int total, const void* midx, long long N) {
    int is64 = probe_is64(midx, N);
    int i = blockIdx.x * blockDim.x + threadIdx.x;
    if (i < total) {
        int g = (int)ld_idx(Gp, i, is64);
        atomicAdd(&g_s.cnt[g], 1.0f);
    }
}

// ---------------- kernel MW: M = U U^T,  W = U diag(cnt) U^T ----------------
// grid = ngrp*4 blocks. Each block: 8 consecutive 16-column chunks (register
// accumulated), one 64x64 quadrant, then ONE atomic store set (32/thread).
__global__ void k_mw(const float* __restrict__ U, int P) {
    __shared__ float sh[16][D_DIM];
    __shared__ float shc[16];

    int grp  = blockIdx.x >> 2;
    int quad = blockIdx.x & 3;
    int tid = threadIdx.x;

    int ti = tid & 15, tj = tid >> 4;
    int i0 = (quad & 1) * 64 + ti * 4;
    int j0 = (quad >> 1) * 64 + tj * 4;

    float m[4][4] = {{0}}, w[4][4] = {{0}};

    for (int c = 0; c < 8; c++) {
        int p0 = (grp * 8 + c) * 16;
        __syncthreads();
        for (int e = tid; e < 16 * D_DIM; e += blockDim.x) {
            int d = e >> 4, pc = e & 15;
            int p = p0 + pc;
            sh[pc][d] = (p < P) ? U[(size_t)d * P + p] : 0.f;
        }
        if (tid < 16) {
            int p = p0 + tid;
            shc[tid] = (p < P) ? g_s.cnt[p] : 0.f;
        }
        __syncthreads();

#pragma unroll
        for (int pc = 0; pc < 16; pc++) {
            float cw = shc[pc];
            float a[4], ca[4], b[4];
#pragma unroll
            for (int x = 0; x < 4; x++) { a[x] = sh[pc][i0 + x]; ca[x] = cw * a[x]; }
#pragma unroll
            for (int y = 0; y < 4; y++) b[y] = sh[pc][j0 + y];
#pragma unroll
            for (int x = 0; x < 4; x++)
#pragma unroll
                for (int y = 0; y < 4; y++) {
                    m[x][y] += a[x] * b[y];
                    w[x][y] += ca[x] * b[y];
                }
        }
    }

#pragma unroll
    for (int x = 0; x < 4; x++)
#pragma unroll
        for (int y = 0; y < 4; y++) {
            int idx = (i0 + x) * D_DIM + (j0 + y);
            atomicAdd(&g_s.M[idx], m[x][y]);
            atomicAdd(&g_s.W[idx], w[x][y]);
        }
}

// ---------------- kernel D: the big HBM-bound dots pass (R1 form) ----------
__global__ void __launch_bounds__(256)
k_dots(const float* __restrict__ Ub, const float* __restrict__ U,
       const void* midx, const void* segs,
       long long N, int P) {
    int is64 = probe_is64(midx, N);
    long long j = (long long)blockIdx.x * blockDim.x + threadIdx.x;

    double val = 0.0;
    if (j < N) {
        long long mi = ld_idx(midx, j, is64);
        int g = (int)ld_idx(segs, j, is64);
        const float* ub = Ub + mi;
        const float* uu = U + g;
        float acc0 = 0.f, acc1 = 0.f;
#pragma unroll 16
        for (int d = 0; d < D_DIM; d += 2) {
            acc0 += __ldg(ub + (size_t)d * N)       * __ldg(uu + (size_t)d * P);
            acc1 += __ldg(ub + (size_t)(d + 1) * N) * __ldg(uu + (size_t)(d + 1) * P);
        }
        float acc = acc0 + acc1;
        val = (double)acc * (double)acc;
    }

    // block reduce (256 threads) in double
    __shared__ double red[8];
    unsigned mask = 0xFFFFFFFFu;
#pragma unroll
    for (int off = 16; off > 0; off >>= 1)
        val += __shfl_down_sync(mask, val, off);
    int lane = threadIdx.x & 31, warp = threadIdx.x >> 5;
    if (lane == 0) red[warp] = val;
    __syncthreads();
    if (warp == 0) {
        double s = (lane < 8) ? red[lane] : 0.0;
#pragma unroll
        for (int off = 4; off > 0; off >>= 1)
            s += __shfl_down_sync(mask, s, off);
        if (lane == 0) atomicAdd(&g_s.acc, s);
    }
}

// ---------------- kernel F: trace(M .* W) + finalize (latency-pipelined) ----
__global__ void __launch_bounds__(1024)
k_final(float* out, double inv_den) {
    __shared__ double red[32];
    int tid = threadIdx.x;               // 1024 threads, 16 elements each
    int base = tid * 16;

    double s = 0.0;
#pragma unroll
    for (int q = 0; q < 4; q++) {
        float4 mv = __ldg((const float4*)(g_s.M + base + q * 4));
        float4 wv = __ldg((const float4*)(g_s.W + base + q * 4));
        s += (double)mv.x * wv.x + (double)mv.y * wv.y
           + (double)mv.z * wv.z + (double)mv.w * wv.w;
    }

    unsigned mask = 0xFFFFFFFFu;
#pragma unroll
    for (int off = 16; off > 0; off >>= 1)
        s += __shfl_down_sync(mask, s, off);
    int lane = tid & 31, warp = tid >> 5;
    if (lane == 0) red[warp] = s;
    __syncthreads();
    if (warp == 0) {
        double t = red[lane];
#pragma unroll
        for (int off = 16; off > 0; off >>= 1)
            t += __shfl_down_sync(mask, t, off);
        if (lane == 0)
            out[0] = (float)(-0.5 * g_s.acc - 0.5 * t * inv_den);
    }
}

// ---------------- launch ----------------
extern "C" void kernel_launch(void* const* d_in, const int* in_sizes, int n_in,
                              void* d_out, int out_size) {
    const float* U_base = (const float*)d_in[0];
    const float* U      = (const float*)d_in[1];
    const void*  midx   = d_in[2];
    const void*  segs   = d_in[3];
    const void*  Gp     = d_in[4];

    long long N = in_sizes[2];
    int D = (int)((long long)in_sizes[0] / N); // = 128
    int P = in_sizes[1] / D;                   // = 1024
    int PK = in_sizes[4];                      // P*K
    int K = PK / P;
    (void)D; (void)n_in;

    float* out = (float*)d_out;
    (void)out_size;

    // Zero ALL scratch with one memset node (graph-capturable, no allocation).
    void* pS;
    cudaGetSymbolAddress(&pS, g_s);
    cudaMemsetAsync(pS, 0, sizeof(Scratch));

    // H: histogram of G (self-probes index dtype)
    k_hist<<<(PK + 255) / 256, 256>>>(Gp, PK, midx, N);

    // MW: dual weighted outer-product, 8 chunks per block
    int nchunk = (P + 15) / 16;
    int ngrp = (nchunk + 7) / 8;
    k_mw<<<ngrp * 4, 256>>>(U, P);

    // D: main HBM-bound pass (1 j per thread, 256 threads/block)
    long long nblk = (N + 255) / 256;
    k_dots<<<(unsigned)nblk, 256>>>(U_base, U, midx, segs, N, P);

    // F: finalize
    double inv_den = 1.0 / ((double)P * (double)K * (double)P);
    k_final<<<1, 1024>>>(out, inv_den);
}